// round 1
// baseline (speedup 1.0000x reference)
#include <cuda_runtime.h>
#include <cstdint>

#define N_DIM   256
#define BS      256
#define TMAX    1000
#define STEP_F  0.01f
#define EPS_F   0.001f

#define CLUSTER 2
#define HALF    128            // rows of A / x per CTA
#define CPC     4              // batch columns per cluster
#define NCLUST  (BS / CPC)     // 64 clusters
#define GRID    (NCLUST * CLUSTER)  // 128 CTAs
#define THREADS 256

#define A_LD    260            // padded row stride (floats): (4r+j)%32 distinct -> conflict-free LDS.128
#define X_LD    264            // padded x column stride (floats), 16B-aligned

// dynamic smem layout (floats):
//   sA  [HALF * A_LD]            130.0 KB
//   sX  [2][CPC][X_LD]             8.25 KB  (double-buffered full 256-length x per column)
//   sRed[HALF * CPC]               2.0 KB
//   sBy [HALF]                     0.5 KB
#define SMEM_FLOATS (HALF * A_LD + 2 * CPC * X_LD + HALF * CPC + HALF)
#define SMEM_BYTES  (SMEM_FLOATS * 4)

union F4 { float4 v; float2 h[2]; };

__device__ __forceinline__ void fma2(float2& d, const float2& a, const float2& b) {
    asm("fma.rn.f32x2 %0, %1, %2, %0;"
        : "+l"(reinterpret_cast<unsigned long long&>(d))
        : "l"(reinterpret_cast<const unsigned long long&>(a)),
          "l"(reinterpret_cast<const unsigned long long&>(b)));
}

__device__ __forceinline__ uint32_t smem_u32(const void* p) {
    uint32_t a;
    asm("{ .reg .u64 t; cvta.to.shared.u64 t, %1; cvt.u32.u64 %0, t; }" : "=r"(a) : "l"(p));
    return a;
}

__device__ __forceinline__ void st_dsmem_f32(uint32_t addr, float v) {
    asm volatile("st.shared::cluster.b32 [%0], %1;" :: "r"(addr), "r"(__float_as_uint(v)) : "memory");
}

__device__ __forceinline__ void cluster_sync_() {
    asm volatile("barrier.cluster.arrive.aligned;" ::: "memory");
    asm volatile("barrier.cluster.wait.aligned;" ::: "memory");
}

extern "C" __global__ void __launch_bounds__(THREADS, 1) __cluster_dims__(CLUSTER, 1, 1)
antisym_rnn_kernel(const float* __restrict__ X0,
                   const float* __restrict__ W,
                   const float* __restrict__ by,
                   float* __restrict__ out)
{
    extern __shared__ float smem[];
    float* sA   = smem;                          // [HALF][A_LD]
    float* sX   = sA + HALF * A_LD;              // [2][CPC][X_LD]
    float* sRed = sX + 2 * CPC * X_LD;           // [HALF][CPC]
    float* sBy  = sRed + HALF * CPC;             // [HALF]

    const int tid = threadIdx.x;
    uint32_t rank;
    asm("mov.u32 %0, %%cluster_ctarank;" : "=r"(rank));
    const int half      = (int)rank;                 // 0 or 1
    const int clusterId = blockIdx.x / CLUSTER;
    const int col0      = clusterId * CPC;           // first batch column of this cluster
    const int row_base  = half * HALF;               // global row range [row_base, row_base+128)

    // ---- one-time init: build A half from W (A = triu(W,1) - triu(W,1)^T - eps*I) ----
    for (int idx = tid; idx < HALF * N_DIM; idx += THREADS) {
        int r = idx >> 8;              // local row
        int j = idx & 255;             // column
        int i = row_base + r;          // global row
        float v;
        if (j > i)      v =  W[i * N_DIM + j];
        else if (j < i) v = -W[j * N_DIM + i];
        else            v = -EPS_F;
        sA[r * A_LD + j] = v;
    }
    for (int r = tid; r < HALF; r += THREADS) sBy[r] = by[row_base + r];

    // x0 (full 256-length vector per column; each CTA loads its own full copy)
    for (int idx = tid; idx < CPC * N_DIM; idx += THREADS) {
        int c = idx >> 8;
        int j = idx & 255;
        sX[c * X_LD + j] = X0[(col0 + c) * N_DIM + j];
    }
    // t = 0 snapshot: this CTA writes its row half for its columns
    for (int idx = tid; idx < CPC * HALF; idx += THREADS) {
        int c = idx / HALF;
        int r = idx - c * HALF;
        size_t ob = (size_t)(col0 + c) * (TMAX * N_DIM);
        out[ob + (row_base + r)] = X0[(col0 + c) * N_DIM + row_base + r];
    }

    // peer CTA's sX base address (cluster shared window)
    uint32_t sx_local = smem_u32(sX);
    uint32_t sx_peer;
    {
        uint32_t peer_rank = 1u - rank;
        asm("mapa.shared::cluster.u32 %0, %1, %2;" : "=r"(sx_peer) : "r"(sx_local), "r"(peer_rank));
    }

    __syncthreads();
    cluster_sync_();

    const int r  = tid & (HALF - 1);     // local output row
    const int jh = tid >> 7;             // K-half (0 or 1)
    const int row_g = row_base + r;      // global row
    const float* Arow = sA + r * A_LD + jh * (N_DIM / 2);
    const float byv = sBy[r];

    int buf = 0;
    for (int t = 1; t < TMAX; ++t) {
        const float* xb = sX + buf * CPC * X_LD + jh * (N_DIM / 2);
        const float* xc0 = xb + 0 * X_LD;
        const float* xc1 = xb + 1 * X_LD;
        const float* xc2 = xb + 2 * X_LD;
        const float* xc3 = xb + 3 * X_LD;

        float2 a0 = {0.f, 0.f}, b0 = {0.f, 0.f};
        float2 a1 = {0.f, 0.f}, b1 = {0.f, 0.f};
        float2 a2 = {0.f, 0.f}, b2 = {0.f, 0.f};
        float2 a3 = {0.f, 0.f}, b3 = {0.f, 0.f};

        #pragma unroll 8
        for (int j = 0; j < N_DIM / 2; j += 4) {
            F4 av;  av.v  = *reinterpret_cast<const float4*>(Arow + j);
            F4 x0v; x0v.v = *reinterpret_cast<const float4*>(xc0 + j);
            F4 x1v; x1v.v = *reinterpret_cast<const float4*>(xc1 + j);
            F4 x2v; x2v.v = *reinterpret_cast<const float4*>(xc2 + j);
            F4 x3v; x3v.v = *reinterpret_cast<const float4*>(xc3 + j);
            fma2(a0, av.h[0], x0v.h[0]);  fma2(b0, av.h[1], x0v.h[1]);
            fma2(a1, av.h[0], x1v.h[0]);  fma2(b1, av.h[1], x1v.h[1]);
            fma2(a2, av.h[0], x2v.h[0]);  fma2(b2, av.h[1], x2v.h[1]);
            fma2(a3, av.h[0], x3v.h[0]);  fma2(b3, av.h[1], x3v.h[1]);
        }

        float p0 = (a0.x + a0.y) + (b0.x + b0.y);
        float p1 = (a1.x + a1.y) + (b1.x + b1.y);
        float p2 = (a2.x + a2.y) + (b2.x + b2.y);
        float p3 = (a3.x + a3.y) + (b3.x + b3.y);

        if (jh == 1) {
            sRed[r * CPC + 0] = p0;
            sRed[r * CPC + 1] = p1;
            sRed[r * CPC + 2] = p2;
            sRed[r * CPC + 3] = p3;
        }
        __syncthreads();

        const int nbuf = buf ^ 1;
        if (jh == 0) {
            float y0 = p0 + sRed[r * CPC + 0] + byv;
            float y1 = p1 + sRed[r * CPC + 1] + byv;
            float y2 = p2 + sRed[r * CPC + 2] + byv;
            float y3 = p3 + sRed[r * CPC + 3] + byv;

            const float* xcur = sX + buf * CPC * X_LD;
            float xn0 = xcur[0 * X_LD + row_g] + STEP_F * tanhf(y0);
            float xn1 = xcur[1 * X_LD + row_g] + STEP_F * tanhf(y1);
            float xn2 = xcur[2 * X_LD + row_g] + STEP_F * tanhf(y2);
            float xn3 = xcur[3 * X_LD + row_g] + STEP_F * tanhf(y3);

            float* xnext = sX + nbuf * CPC * X_LD;
            xnext[0 * X_LD + row_g] = xn0;
            xnext[1 * X_LD + row_g] = xn1;
            xnext[2 * X_LD + row_g] = xn2;
            xnext[3 * X_LD + row_g] = xn3;

            uint32_t pbase = sx_peer + (uint32_t)(nbuf * CPC * X_LD + row_g) * 4u;
            st_dsmem_f32(pbase + 0u * X_LD * 4u, xn0);
            st_dsmem_f32(pbase + 1u * X_LD * 4u, xn1);
            st_dsmem_f32(pbase + 2u * X_LD * 4u, xn2);
            st_dsmem_f32(pbase + 3u * X_LD * 4u, xn3);

            size_t tb = (size_t)t * N_DIM + row_g;
            out[(size_t)(col0 + 0) * (TMAX * N_DIM) + tb] = xn0;
            out[(size_t)(col0 + 1) * (TMAX * N_DIM) + tb] = xn1;
            out[(size_t)(col0 + 2) * (TMAX * N_DIM) + tb] = xn2;
            out[(size_t)(col0 + 3) * (TMAX * N_DIM) + tb] = xn3;
        }

        cluster_sync_();   // publishes DSMEM halves of x_{t+1}; also protects buffer reuse
        buf = nbuf;
    }
}

extern "C" void kernel_launch(void* const* d_in, const int* in_sizes, int n_in,
                              void* d_out, int out_size) {
    const float* X0 = (const float*)d_in[0];
    const float* W  = (const float*)d_in[1];
    const float* by = (const float*)d_in[2];
    float* out = (float*)d_out;

    cudaFuncSetAttribute(antisym_rnn_kernel,
                         cudaFuncAttributeMaxDynamicSharedMemorySize, SMEM_BYTES);
    antisym_rnn_kernel<<<GRID, THREADS, SMEM_BYTES>>>(X0, W, by, out);
}

// round 2
// speedup vs baseline: 1.6289x; 1.6289x over previous
#include <cuda_runtime.h>
#include <cstdint>

#define N_DIM   256
#define BS      256
#define TMAX    1000
#define STEP_F  0.01f
#define EPS_F   0.001f

#define CPC     2                 // batch columns per CTA
#define GRID    (BS / CPC)        // 128 CTAs
#define THREADS 256               // 8 warps

// Per-warp layout: warp w owns rows [w*32, w*32+32).
// Lane l: rg = l>>3 (row-group 0..3), kl = l&7 (K-slice [kl*32, kl*32+32)).
// Thread rows: w*32 + rg*8 + i, i in [0,8). i<4 -> A in registers, i>=4 -> A in smem.

// smem: sA float4[8192] = 128KB, conflict-free layout:
//   f4 index = ((i4*8 + j)*8 + w)*32 + l      (i4 = i-4, j = K-chunk 0..7)
// sX float[2 buf][2 col][256] with permuted word layout p(k):
//   k = kl*32 + j*4 + e  ->  p = j*32 + kl*4 + e   (lane-contiguous float4 chunks)
// sBy float[256]
#define SA_F4      8192
#define SX_FLOATS  (2 * 2 * 256)
#define SMEM_BYTES (SA_F4 * 16 + (SX_FLOATS + 256) * 4)

union F4 { float4 v; float2 h[2]; };

__device__ __forceinline__ void fma2(float2& d, const float2& a, const float2& b) {
    asm("fma.rn.f32x2 %0, %1, %2, %0;"
        : "+l"(reinterpret_cast<unsigned long long&>(d))
        : "l"(reinterpret_cast<const unsigned long long&>(a)),
          "l"(reinterpret_cast<const unsigned long long&>(b)));
}

__device__ __forceinline__ int permx(int k) {
    // k = (kl<<5) | (j<<2) | e  ->  (j<<5) | (kl<<2) | e
    return (((k >> 2) & 7) << 5) | ((k >> 5) << 2) | (k & 3);
}

__device__ __forceinline__ float a_elem(const float* __restrict__ W, int r, int k) {
    if (k > r) return  __ldg(&W[r * N_DIM + k]);
    if (k < r) return -__ldg(&W[k * N_DIM + r]);
    return -EPS_F;
}

// Butterfly reduce-scatter over 8-lane group: vals[8] -> lane kl owns sum of vals[kl].
__device__ __forceinline__ float reduce8(float* v, int kl) {
    {   bool hi = (kl & 4) != 0;
        #pragma unroll
        for (int i = 0; i < 4; i++) {
            float send = hi ? v[i] : v[i + 4];
            float recv = __shfl_xor_sync(0xffffffffu, send, 4);
            v[i] = (hi ? v[i + 4] : v[i]) + recv;
        }
    }
    {   bool hi = (kl & 2) != 0;
        #pragma unroll
        for (int i = 0; i < 2; i++) {
            float send = hi ? v[i] : v[i + 2];
            float recv = __shfl_xor_sync(0xffffffffu, send, 2);
            v[i] = (hi ? v[i + 2] : v[i]) + recv;
        }
    }
    {   bool hi = (kl & 1) != 0;
        float send = hi ? v[0] : v[1];
        float recv = __shfl_xor_sync(0xffffffffu, send, 1);
        return (hi ? v[1] : v[0]) + recv;
    }
}

extern "C" __global__ void __launch_bounds__(THREADS, 1)
antisym_rnn_kernel(const float* __restrict__ X0,
                   const float* __restrict__ W,
                   const float* __restrict__ by,
                   float* __restrict__ out)
{
    extern __shared__ float smem[];
    float4* sA  = reinterpret_cast<float4*>(smem);          // [8192] f4
    float*  sX  = smem + SA_F4 * 4;                         // [2][2][256]
    float*  sBy = sX + SX_FLOATS;                           // [256]

    const int tid = threadIdx.x;
    const int w   = tid >> 5;          // warp 0..7
    const int l   = tid & 31;          // lane
    const int rg  = l >> 3;            // row-group 0..3
    const int kl  = l & 7;             // K-lane 0..7
    const int col0 = blockIdx.x * CPC;
    const int row_base = w * 32 + rg * 8;   // this thread's 8 rows start here
    const int k_base   = kl * 32;           // this thread's K slice

    // ---- one-time init ----
    // A register half: rows row_base + i, i in [0,4)
    float4 areg[4][8];
    #pragma unroll
    for (int i = 0; i < 4; i++) {
        int r = row_base + i;
        #pragma unroll
        for (int j = 0; j < 8; j++) {
            int k = k_base + j * 4;
            areg[i][j] = make_float4(a_elem(W, r, k),     a_elem(W, r, k + 1),
                                     a_elem(W, r, k + 2), a_elem(W, r, k + 3));
        }
    }
    // A smem half: rows row_base + 4 + i4
    #pragma unroll
    for (int i4 = 0; i4 < 4; i4++) {
        int r = row_base + 4 + i4;
        #pragma unroll
        for (int j = 0; j < 8; j++) {
            int k = k_base + j * 4;
            sA[((i4 * 8 + j) * 8 + w) * 32 + l] =
                make_float4(a_elem(W, r, k),     a_elem(W, r, k + 1),
                            a_elem(W, r, k + 2), a_elem(W, r, k + 3));
        }
    }
    // by, x0, t=0 output
    sBy[tid] = by[tid];
    #pragma unroll
    for (int c = 0; c < CPC; c++) {
        float v = X0[(col0 + c) * N_DIM + tid];
        sX[(0 * 2 + c) * 256 + permx(tid)] = v;
        out[(size_t)(col0 + c) * (TMAX * N_DIM) + tid] = v;
    }
    __syncthreads();

    const int  my_row = row_base + kl;     // row this lane owns after reduction
    const float byv   = sBy[my_row];

    int buf = 0;
    for (int t = 1; t < TMAX; ++t) {
        const float4* x0p = reinterpret_cast<const float4*>(sX + (buf * 2 + 0) * 256);
        const float4* x1p = reinterpret_cast<const float4*>(sX + (buf * 2 + 1) * 256);

        // ---- pass 1: register-A rows (i = 0..3) ----
        float2 acc[4][2];
        #pragma unroll
        for (int i = 0; i < 4; i++) { acc[i][0] = make_float2(0.f, 0.f);
                                      acc[i][1] = make_float2(0.f, 0.f); }
        #pragma unroll
        for (int j = 0; j < 8; j++) {
            F4 xa; xa.v = x0p[j * 8 + kl];
            F4 xb; xb.v = x1p[j * 8 + kl];
            #pragma unroll
            for (int i = 0; i < 4; i++) {
                F4 a; a.v = areg[i][j];
                fma2(acc[i][0], a.h[0], xa.h[0]); fma2(acc[i][0], a.h[1], xa.h[1]);
                fma2(acc[i][1], a.h[0], xb.h[0]); fma2(acc[i][1], a.h[1], xb.h[1]);
            }
        }

        // ---- pass 2: smem-A rows (i = 4..7) ----
        float2 acc2[4][2];
        #pragma unroll
        for (int i = 0; i < 4; i++) { acc2[i][0] = make_float2(0.f, 0.f);
                                      acc2[i][1] = make_float2(0.f, 0.f); }
        #pragma unroll 4
        for (int j = 0; j < 8; j++) {
            F4 xa; xa.v = x0p[j * 8 + kl];
            F4 xb; xb.v = x1p[j * 8 + kl];
            #pragma unroll
            for (int i4 = 0; i4 < 4; i4++) {
                F4 a; a.v = sA[((i4 * 8 + j) * 8 + w) * 32 + l];
                fma2(acc2[i4][0], a.h[0], xa.h[0]); fma2(acc2[i4][0], a.h[1], xa.h[1]);
                fma2(acc2[i4][1], a.h[0], xb.h[0]); fma2(acc2[i4][1], a.h[1], xb.h[1]);
            }
        }

        // collapse to scalars: vals[c][i], i row-offset 0..7
        float v0[8], v1[8];
        #pragma unroll
        for (int i = 0; i < 4; i++) {
            v0[i]     = acc[i][0].x  + acc[i][0].y;
            v1[i]     = acc[i][1].x  + acc[i][1].y;
            v0[i + 4] = acc2[i][0].x + acc2[i][0].y;
            v1[i + 4] = acc2[i][1].x + acc2[i][1].y;
        }

        // cross-K reduction within 8-lane group; lane kl ends owning row row_base+kl
        float y0 = reduce8(v0, kl) + byv;
        float y1 = reduce8(v1, kl) + byv;

        const int nbuf = buf ^ 1;
        const int pr = permx(my_row);
        float xp0 = sX[(buf * 2 + 0) * 256 + pr];
        float xp1 = sX[(buf * 2 + 1) * 256 + pr];
        float xn0 = xp0 + STEP_F * tanhf(y0);
        float xn1 = xp1 + STEP_F * tanhf(y1);
        sX[(nbuf * 2 + 0) * 256 + pr] = xn0;
        sX[(nbuf * 2 + 1) * 256 + pr] = xn1;

        size_t tb = (size_t)t * N_DIM + my_row;
        out[(size_t)(col0 + 0) * (TMAX * N_DIM) + tb] = xn0;
        out[(size_t)(col0 + 1) * (TMAX * N_DIM) + tb] = xn1;

        __syncthreads();
        buf = nbuf;
    }
}

extern "C" void kernel_launch(void* const* d_in, const int* in_sizes, int n_in,
                              void* d_out, int out_size) {
    const float* X0 = (const float*)d_in[0];
    const float* W  = (const float*)d_in[1];
    const float* by = (const float*)d_in[2];
    float* out = (float*)d_out;

    cudaFuncSetAttribute(antisym_rnn_kernel,
                         cudaFuncAttributeMaxDynamicSharedMemorySize, SMEM_BYTES);
    antisym_rnn_kernel<<<GRID, THREADS, SMEM_BYTES>>>(X0, W, by, out);
}

// round 3
// speedup vs baseline: 2.0803x; 1.2771x over previous
#include <cuda_runtime.h>
#include <cstdint>

#define N_DIM   256
#define BS      256
#define TMAX    1000
#define STEP_F  0.01f
#define EPS_F   0.001f

#define CPC     2                 // batch columns per CTA
#define GRID    (BS / CPC)        // 128 CTAs
#define THREADS 256               // 8 warps

// Per-warp layout: warp w owns rows [w*32, w*32+32).
// Lane l: rg = l>>3 (row-group 0..3), kl = l&7 (K-slice [kl*32, kl*32+32)).
// Thread rows: w*32 + rg*8 + i, i in [0,8). i<4 -> A in registers, i>=4 -> A in smem.
// After the 8-lane butterfly reduction lane l owns row w*32 + rg*8 + kl = w*32 + l.

#define SA_F4      8192           // 128 KB of A in smem
#define SX_FLOATS  (2 * 2 * 256)  // double-buffered x, 2 columns, permuted layout
#define SMEM_BYTES (SA_F4 * 16 + SX_FLOATS * 4)

union F4 { float4 v; float2 h[2]; };

__device__ __forceinline__ void fma2(float2& d, const float2& a, const float2& b) {
    asm("fma.rn.f32x2 %0, %1, %2, %0;"
        : "+l"(reinterpret_cast<unsigned long long&>(d))
        : "l"(reinterpret_cast<const unsigned long long&>(a)),
          "l"(reinterpret_cast<const unsigned long long&>(b)));
}

__device__ __forceinline__ int permx(int k) {
    // k = (kl<<5) | (j<<2) | e  ->  (j<<5) | (kl<<2) | e
    return (((k >> 2) & 7) << 5) | ((k >> 5) << 2) | (k & 3);
}

__device__ __forceinline__ float a_elem(const float* __restrict__ W, int r, int k) {
    if (k > r) return  __ldg(&W[r * N_DIM + k]);
    if (k < r) return -__ldg(&W[k * N_DIM + r]);
    return -EPS_F;
}

// Accurate fast tanh: tanh(|y|) = 1 - 2/(exp(2|y|)+1), via ex2.approx + rcp.approx.
// Abs error ~1e-7; large |y| saturates exactly to +/-1 (ex2 -> inf, rcp -> 0).
__device__ __forceinline__ float fast_tanh(float y) {
    float ay = fabsf(y);
    float e;
    asm("ex2.approx.f32 %0, %1;" : "=f"(e) : "f"(ay * 2.8853900817779268f)); // 2*log2(e)
    float r;
    asm("rcp.approx.f32 %0, %1;" : "=f"(r) : "f"(e + 1.0f));
    float t = fmaf(-2.0f, r, 1.0f);
    return copysignf(t, y);
}

// Butterfly reduce-scatter over 8-lane group: vals[8] -> lane kl owns sum of vals[kl].
__device__ __forceinline__ float reduce8(float* v, int kl) {
    {   bool hi = (kl & 4) != 0;
        #pragma unroll
        for (int i = 0; i < 4; i++) {
            float send = hi ? v[i] : v[i + 4];
            float recv = __shfl_xor_sync(0xffffffffu, send, 4);
            v[i] = (hi ? v[i + 4] : v[i]) + recv;
        }
    }
    {   bool hi = (kl & 2) != 0;
        #pragma unroll
        for (int i = 0; i < 2; i++) {
            float send = hi ? v[i] : v[i + 2];
            float recv = __shfl_xor_sync(0xffffffffu, send, 2);
            v[i] = (hi ? v[i + 2] : v[i]) + recv;
        }
    }
    {   bool hi = (kl & 1) != 0;
        float send = hi ? v[0] : v[1];
        float recv = __shfl_xor_sync(0xffffffffu, send, 1);
        return (hi ? v[1] : v[0]) + recv;
    }
}

extern "C" __global__ void __launch_bounds__(THREADS, 1)
antisym_rnn_kernel(const float* __restrict__ X0,
                   const float* __restrict__ W,
                   const float* __restrict__ by,
                   float* __restrict__ out)
{
    extern __shared__ float smem[];
    float4* sA = reinterpret_cast<float4*>(smem);           // [8192] f4
    float*  sX = smem + SA_F4 * 4;                          // [2][2][256] permuted

    const int tid = threadIdx.x;
    const int w   = tid >> 5;          // warp 0..7
    const int l   = tid & 31;          // lane
    const int rg  = l >> 3;            // row-group 0..3
    const int kl  = l & 7;             // K-lane 0..7
    const int col0 = blockIdx.x * CPC;
    const int row_base = w * 32 + rg * 8;   // this thread's 8 rows start here
    const int k_base   = kl * 32;           // this thread's K slice
    const int my_row   = w * 32 + l;        // row this lane owns after reduction

    // ---- one-time init ----
    float4 areg[4][8];
    #pragma unroll
    for (int i = 0; i < 4; i++) {
        int r = row_base + i;
        #pragma unroll
        for (int j = 0; j < 8; j++) {
            int k = k_base + j * 4;
            areg[i][j] = make_float4(a_elem(W, r, k),     a_elem(W, r, k + 1),
                                     a_elem(W, r, k + 2), a_elem(W, r, k + 3));
        }
    }
    #pragma unroll
    for (int i4 = 0; i4 < 4; i4++) {
        int r = row_base + 4 + i4;
        #pragma unroll
        for (int j = 0; j < 8; j++) {
            int k = k_base + j * 4;
            sA[((i4 * 8 + j) * 8 + w) * 32 + l] =
                make_float4(a_elem(W, r, k),     a_elem(W, r, k + 1),
                            a_elem(W, r, k + 2), a_elem(W, r, k + 3));
        }
    }
    const float byv = by[my_row];

    // x0 into both: permuted smem and this lane's own-row register
    #pragma unroll
    for (int c = 0; c < CPC; c++) {
        float v = X0[(col0 + c) * N_DIM + tid];
        sX[(0 * 2 + c) * 256 + permx(tid)] = v;
        out[(size_t)(col0 + c) * (TMAX * N_DIM) + tid] = v;
    }
    float xr0 = X0[(col0 + 0) * N_DIM + my_row];
    float xr1 = X0[(col0 + 1) * N_DIM + my_row];
    __syncthreads();

    int buf = 0;
    for (int t = 1; t < TMAX; ++t) {
        const float4* x0p = reinterpret_cast<const float4*>(sX + (buf * 2 + 0) * 256);
        const float4* x1p = reinterpret_cast<const float4*>(sX + (buf * 2 + 1) * 256);

        float2 acc[8][2];
        #pragma unroll
        for (int i = 0; i < 8; i++) { acc[i][0] = make_float2(0.f, 0.f);
                                      acc[i][1] = make_float2(0.f, 0.f); }

        // fused matvec: load each x chunk once, feed reg-A and smem-A rows
        #pragma unroll
        for (int j = 0; j < 8; j++) {
            F4 xa; xa.v = x0p[j * 8 + kl];
            F4 xb; xb.v = x1p[j * 8 + kl];
            #pragma unroll
            for (int i = 0; i < 4; i++) {
                F4 a; a.v = areg[i][j];
                fma2(acc[i][0], a.h[0], xa.h[0]); fma2(acc[i][0], a.h[1], xa.h[1]);
                fma2(acc[i][1], a.h[0], xb.h[0]); fma2(acc[i][1], a.h[1], xb.h[1]);
            }
            #pragma unroll
            for (int i4 = 0; i4 < 4; i4++) {
                F4 a; a.v = sA[((i4 * 8 + j) * 8 + w) * 32 + l];
                fma2(acc[4 + i4][0], a.h[0], xa.h[0]); fma2(acc[4 + i4][0], a.h[1], xa.h[1]);
                fma2(acc[4 + i4][1], a.h[0], xb.h[0]); fma2(acc[4 + i4][1], a.h[1], xb.h[1]);
            }
        }

        float v0[8], v1[8];
        #pragma unroll
        for (int i = 0; i < 8; i++) {
            v0[i] = acc[i][0].x + acc[i][0].y;
            v1[i] = acc[i][1].x + acc[i][1].y;
        }

        float y0 = reduce8(v0, kl) + byv;
        float y1 = reduce8(v1, kl) + byv;

        float xn0 = xr0 + STEP_F * fast_tanh(y0);
        float xn1 = xr1 + STEP_F * fast_tanh(y1);
        xr0 = xn0; xr1 = xn1;

        const int nbuf = buf ^ 1;
        const int pr = permx(my_row);
        sX[(nbuf * 2 + 0) * 256 + pr] = xn0;
        sX[(nbuf * 2 + 1) * 256 + pr] = xn1;

        size_t tb = (size_t)t * N_DIM + my_row;
        out[(size_t)(col0 + 0) * (TMAX * N_DIM) + tb] = xn0;
        out[(size_t)(col0 + 1) * (TMAX * N_DIM) + tb] = xn1;

        __syncthreads();
        buf = nbuf;
    }
}

extern "C" void kernel_launch(void* const* d_in, const int* in_sizes, int n_in,
                              void* d_out, int out_size) {
    const float* X0 = (const float*)d_in[0];
    const float* W  = (const float*)d_in[1];
    const float* by = (const float*)d_in[2];
    float* out = (float*)d_out;

    cudaFuncSetAttribute(antisym_rnn_kernel,
                         cudaFuncAttributeMaxDynamicSharedMemorySize, SMEM_BYTES);
    antisym_rnn_kernel<<<GRID, THREADS, SMEM_BYTES>>>(X0, W, by, out);
}